// round 7
// baseline (speedup 1.0000x reference)
#include <cuda_runtime.h>

#define LEAK 0.2f
constexpr int B_  = 2;
constexpr int C_  = 16;
constexpr int VOL = 96 * 96 * 96;
constexpr int PLN = 96 * 96;
constexpr int DVF = 48;

typedef unsigned long long pk_t;

// Scratch (device globals per harness rules).
__device__ float g_warped[(size_t)B_ * C_ * VOL];  // warped src; later fsum
__device__ float g_corr[(size_t)B_ * 27 * VOL];    // cost volume
__device__ float g_facc[(size_t)B_ * C_ * VOL];    // conv1 out (f)

__device__ __forceinline__ float lrelu(float v) { return v > 0.f ? v : LEAK * v; }

__device__ __forceinline__ pk_t pack2(float lo, float hi) {
    pk_t r; asm("mov.b64 %0, {%1,%2};" : "=l"(r) : "f"(lo), "f"(hi)); return r;
}
__device__ __forceinline__ void unpack2(pk_t p, float& lo, float& hi) {
    asm("mov.b64 {%0,%1}, %2;" : "=f"(lo), "=f"(hi) : "l"(p));
}
__device__ __forceinline__ pk_t ffma2(pk_t a, pk_t b, pk_t c) {
    pk_t d; asm("fma.rn.f32x2 %0, %1, %2, %3;" : "=l"(d) : "l"(a), "l"(b), "l"(c));
    return d;
}

// ---------------------------------------------------------------------------
// K1: trilinear upsample of dvf (48^3 -> 96^3, align_corners) + warp source
// ---------------------------------------------------------------------------
__global__ void warp_kernel(const float* __restrict__ src,
                            const float* __restrict__ dvf)
{
    int idx = blockIdx.x * blockDim.x + threadIdx.x;
    if (idx >= B_ * VOL) return;
    int b = idx / VOL;
    int r = idx - b * VOL;
    int z = r / PLN;
    int y = (r / 96) % 96;
    int x = r % 96;

    const float sc = 47.0f / 95.0f;
    float pz = z * sc, py = y * sc, px = x * sc;
    int z0 = (int)pz, y0 = (int)py, x0 = (int)px;
    int z1 = min(z0 + 1, DVF - 1), y1 = min(y0 + 1, DVF - 1), x1 = min(x0 + 1, DVF - 1);
    float wz = pz - (float)z0, wy = py - (float)y0, wx = px - (float)x0;

    const float* dv = dvf + (size_t)b * 3 * DVF * DVF * DVF;
    float flow[3];
#pragma unroll
    for (int cc = 0; cc < 3; cc++) {
        const float* p = dv + (size_t)cc * DVF * DVF * DVF;
        float v000 = __ldg(p + (z0 * 48 + y0) * 48 + x0);
        float v001 = __ldg(p + (z0 * 48 + y0) * 48 + x1);
        float v010 = __ldg(p + (z0 * 48 + y1) * 48 + x0);
        float v011 = __ldg(p + (z0 * 48 + y1) * 48 + x1);
        float v100 = __ldg(p + (z1 * 48 + y0) * 48 + x0);
        float v101 = __ldg(p + (z1 * 48 + y0) * 48 + x1);
        float v110 = __ldg(p + (z1 * 48 + y1) * 48 + x0);
        float v111 = __ldg(p + (z1 * 48 + y1) * 48 + x1);
        float v00 = v000 * (1.f - wx) + v001 * wx;
        float v01 = v010 * (1.f - wx) + v011 * wx;
        float v10 = v100 * (1.f - wx) + v101 * wx;
        float v11 = v110 * (1.f - wx) + v111 * wx;
        float v0 = v00 * (1.f - wy) + v01 * wy;
        float v1 = v10 * (1.f - wy) + v11 * wy;
        flow[cc] = v0 * (1.f - wz) + v1 * wz;
    }

    float zc = (float)z + flow[0];
    float yc = (float)y + flow[1];
    float xc = (float)x + flow[2];
    float zf = floorf(zc), yf = floorf(yc), xf = floorf(xc);
    float fz = zc - zf, fy = yc - yf, fx = xc - xf;
    int iz0 = (int)zf, iy0 = (int)yf, ix0 = (int)xf;

    int   zi[2] = { iz0, iz0 + 1 };
    int   yi[2] = { iy0, iy0 + 1 };
    int   xi[2] = { ix0, ix0 + 1 };
    float wzv[2] = { 1.f - fz, fz };
    float wyv[2] = { 1.f - fy, fy };
    float wxv[2] = { 1.f - fx, fx };

    int   idx8[8];
    float w8[8];
    int j = 0;
#pragma unroll
    for (int a = 0; a < 2; a++)
#pragma unroll
        for (int bb = 0; bb < 2; bb++)
#pragma unroll
            for (int c2 = 0; c2 < 2; c2++) {
                int zz = zi[a], yy = yi[bb], xx = xi[c2];
                bool valid = (zz >= 0 && zz < 96 && yy >= 0 && yy < 96 &&
                              xx >= 0 && xx < 96);
                int zcl = min(max(zz, 0), 95);
                int ycl = min(max(yy, 0), 95);
                int xcl = min(max(xx, 0), 95);
                idx8[j] = (zcl * 96 + ycl) * 96 + xcl;
                w8[j] = valid ? (wzv[a] * wyv[bb] * wxv[c2]) : 0.f;
                j++;
            }

    const float* sb = src + (size_t)b * C_ * VOL;
    float* ob = g_warped + (size_t)b * C_ * VOL + r;
#pragma unroll
    for (int c = 0; c < C_; c++) {
        const float* sp = sb + (size_t)c * VOL;
        float v = 0.f;
#pragma unroll
        for (int k = 0; k < 8; k++) v = fmaf(w8[k], __ldg(sp + idx8[k]), v);
        ob[(size_t)c * VOL] = v;
    }
}

// ---------------------------------------------------------------------------
// K2: 27-shift cost volume, f32x2 packed, 2 x per thread
// ---------------------------------------------------------------------------
__global__ void __launch_bounds__(256, 2) corrp_kernel(const float* __restrict__ tgt)
{
    constexpr int ZCC = 12, NZCC = 96 / ZCC;
    int bz = blockIdx.z;
    int zc = bz % NZCC; bz /= NZCC;
    int b = bz;
    int tx = threadIdx.x, ty = threadIdx.y;
    int gx = blockIdx.x * 32 + tx * 2;
    int y  = blockIdx.y * 16 + ty;
    int zs = zc * ZCC;

    const float* wb = g_warped + (size_t)b * C_ * VOL;
    const float* tb = tgt + (size_t)b * C_ * VOL;

    for (int z = zs; z < zs + ZCC; z++) {
        pk_t acc[27];
#pragma unroll
        for (int s = 0; s < 27; s++) acc[s] = 0ull;

#pragma unroll 1
        for (int ch = 0; ch < C_; ch++) {
            pk_t t2 = *(const pk_t*)(tb + (size_t)ch * VOL + (size_t)z * PLN + y * 96 + gx);
#pragma unroll
            for (int dz = 0; dz < 3; dz++) {
                int zz = z + dz - 1;
                bool vz = (zz >= 0 && zz <= 95);
#pragma unroll
                for (int dy = 0; dy < 3; dy++) {
                    int yy = y + dy - 1;
                    bool vr = vz && (yy >= 0 && yy <= 95);
                    const float* pr = wb + (size_t)ch * VOL + (size_t)zz * PLN + yy * 96 + gx;
                    float m0 = 0.f, m1 = 0.f, vl = 0.f, vrv = 0.f;
                    if (vr) {
                        float2 m = __ldg((const float2*)pr);
                        m0 = m.x; m1 = m.y;
                        if (gx > 0)  vl  = __ldg(pr - 1);
                        if (gx < 94) vrv = __ldg(pr + 2);
                    }
                    pk_t pL = pack2(vl, m0);
                    pk_t pC = pack2(m0, m1);
                    pk_t pR = pack2(m1, vrv);
                    int s = dz * 9 + dy * 3;
                    acc[s]     = ffma2(t2, pL, acc[s]);
                    acc[s + 1] = ffma2(t2, pC, acc[s + 1]);
                    acc[s + 2] = ffma2(t2, pR, acc[s + 2]);
                }
            }
        }

        float* op = g_corr + (size_t)b * 27 * VOL + (size_t)z * PLN + y * 96 + gx;
#pragma unroll
        for (int s = 0; s < 27; s++) {
            float lo, hi;
            unpack2(acc[s], lo, hi);
            lo = lrelu(lo * 0.0625f);
            hi = lrelu(hi * 0.0625f);
            *(float2*)(op + (size_t)s * VOL) = make_float2(lo, hi);
        }
    }
}

// ---------------------------------------------------------------------------
// Scalar z-ring 3x3x3 conv, software-pipelined input loads (double-buffered).
// Block: (32,4) -> 32x4 xy tile, ZC z-chunk, COG couts, up to 3 CIN segments.
// ---------------------------------------------------------------------------
template<int CIN0, int CIN1, int CIN2, int COUT_TOT, int COG, int ZCc, bool RES>
__global__ void __launch_bounds__(128, 5) convsp_kernel(
    const float* __restrict__ in0, const float* __restrict__ in1,
    const float* __restrict__ in2,
    const float* __restrict__ w, const float* __restrict__ bias,
    float* __restrict__ out, const float* __restrict__ res)
{
    constexpr int CTOT = CIN0 + CIN1 + CIN2;
    constexpr int NCG  = COUT_TOT / COG;
    constexpr int NZCc = 96 / ZCc;
    extern __shared__ float swgt[];   // [ci][tap9][kz3][co]

    int bz = blockIdx.z;
    int zc = bz % NZCc; bz /= NZCc;
    int cg = bz % NCG;  bz /= NCG;
    int b  = bz;
    int co0 = cg * COG;

    int tid = threadIdx.y * 32 + threadIdx.x;
    for (int i = tid; i < CTOT * 27 * COG; i += 128) {
        int co = i % COG;
        int r  = i / COG;
        int kz = r % 3;
        int t  = (r / 3) % 9;
        int ci = r / 27;
        swgt[i] = __ldg(w + ((size_t)(co0 + co) * CTOT + ci) * 27 + kz * 9 + t);
    }
    __syncthreads();

    int x = blockIdx.x * 32 + threadIdx.x;
    int y = blockIdx.y * 4 + threadIdx.y;
    int zs = zc * ZCc;

    bool vxm = (x >= 1), vxp = (x <= 94);
    bool vym = (y >= 1), vyp = (y <= 94);

    const float* base0 = in0 + (size_t)b * CIN0 * VOL + y * 96 + x;
    const float* base1 = (CIN1 > 0) ? in1 + (size_t)b * CIN1 * VOL + y * 96 + x : nullptr;
    const float* base2 = (CIN2 > 0) ? in2 + (size_t)b * CIN2 * VOL + y * 96 + x : nullptr;
    size_t out_base = ((size_t)(b * COUT_TOT + co0)) * VOL + y * 96 + x;

    float bco[COG];
#pragma unroll
    for (int co = 0; co < COG; co++) bco[co] = __ldg(bias + co0 + co);

    float a0[COG], a1[COG], a2[COG];
#pragma unroll
    for (int co = 0; co < COG; co++) { a0[co] = 0.f; a1[co] = 0.f; a2[co] = 0.f; }

    // Guarded 9-tap load of one (ci,z)-plane row group.
#define LOAD9(V, PC)                                                           \
    {                                                                          \
        const float* _p = (PC);                                                \
        V[0] = (vym && vxm) ? __ldg(_p - 97) : 0.f;                            \
        V[1] = vym          ? __ldg(_p - 96) : 0.f;                            \
        V[2] = (vym && vxp) ? __ldg(_p - 95) : 0.f;                            \
        V[3] = vxm          ? __ldg(_p - 1)  : 0.f;                            \
        V[4] =                __ldg(_p);                                       \
        V[5] = vxp          ? __ldg(_p + 1)  : 0.f;                            \
        V[6] = (vyp && vxm) ? __ldg(_p + 95) : 0.f;                            \
        V[7] = vyp          ? __ldg(_p + 96) : 0.f;                            \
        V[8] = (vyp && vxp) ? __ldg(_p + 97) : 0.f;                            \
    }

    // 216 FMAs for one ci using values V and weight row WP.
#define FMAS(V, WP, AP, AC, AN)                                                \
    {                                                                          \
        _Pragma("unroll")                                                      \
        for (int t = 0; t < 9; t++) {                                          \
            const float* wt = (WP) + t * 3 * COG;                              \
            _Pragma("unroll")                                                  \
            for (int co = 0; co < COG; co++)                                   \
                AN[co] = fmaf(V[t], wt[co], AN[co]);                           \
            _Pragma("unroll")                                                  \
            for (int co = 0; co < COG; co++)                                   \
                AC[co] = fmaf(V[t], wt[COG + co], AC[co]);                     \
            _Pragma("unroll")                                                  \
            for (int co = 0; co < COG; co++)                                   \
                AP[co] = fmaf(V[t], wt[2 * COG + co], AP[co]);                 \
        }                                                                      \
    }

    // One ci-segment at plane z, with ci+1 input prefetch (ping-pong va/vb).
#define SEG_LOOP(BASE, CINSEG, CIOFF, AP, AC, AN)                              \
    {                                                                          \
        const float* pz = (BASE) + (size_t)z * PLN;                            \
        float va[9], vb[9];                                                    \
        LOAD9(va, pz);                                                         \
        _Pragma("unroll 1")                                                    \
        for (int ci = 0; ci < (CINSEG); ci += 2) {                             \
            if (ci + 1 < (CINSEG)) LOAD9(vb, pz + (size_t)(ci + 1) * VOL);     \
            const float* wp = swgt + (size_t)((CIOFF) + ci) * 27 * COG;        \
            FMAS(va, wp, AP, AC, AN);                                          \
            if (ci + 1 < (CINSEG)) {                                           \
                if (ci + 2 < (CINSEG)) LOAD9(va, pz + (size_t)(ci + 2) * VOL); \
                FMAS(vb, wp + 27 * COG, AP, AC, AN);                           \
            }                                                                  \
        }                                                                      \
    }

#define CONV_STEP(ZP, AP, AC, AN)                                              \
    {                                                                          \
        int z = (ZP);                                                          \
        if (z >= 0 && z <= 95 && z <= zs + ZCc) {                              \
            SEG_LOOP(base0, CIN0, 0, AP, AC, AN);                              \
            if (CIN1 > 0) { SEG_LOOP(base1, CIN1, CIN0, AP, AC, AN); }         \
            if (CIN2 > 0) { SEG_LOOP(base2, CIN2, CIN0 + CIN1, AP, AC, AN); }  \
        }                                                                      \
        int zo = z - 1;                                                        \
        if (zo >= zs && zo < zs + ZCc) {                                       \
            float* po = out + out_base + (size_t)zo * PLN;                     \
            _Pragma("unroll")                                                  \
            for (int co = 0; co < COG; co++) {                                 \
                float vv = lrelu(AP[co] + bco[co]);                            \
                if (RES) vv += __ldg(res + out_base + (size_t)zo * PLN +       \
                                     (size_t)co * VOL);                        \
                po[(size_t)co * VOL] = vv;                                     \
            }                                                                  \
        }                                                                      \
        _Pragma("unroll")                                                      \
        for (int co = 0; co < COG; co++) AP[co] = 0.f;                         \
    }

    for (int zb = zs - 1; zb <= zs + ZCc; zb += 3) {
        CONV_STEP(zb,     a0, a1, a2);
        CONV_STEP(zb + 1, a1, a2, a0);
        CONV_STEP(zb + 2, a2, a0, a1);
    }
#undef CONV_STEP
#undef SEG_LOOP
#undef FMAS
#undef LOAD9
}

// ---------------------------------------------------------------------------
extern "C" void kernel_launch(void* const* d_in, const int* in_sizes, int n_in,
                              void* d_out, int out_size)
{
    const float* src = (const float*)d_in[0];
    const float* tgt = (const float*)d_in[1];
    const float* dvf = (const float*)d_in[2];
    const float* w1  = (const float*)d_in[3];
    const float* b1  = (const float*)d_in[4];
    const float* w2  = (const float*)d_in[5];
    const float* b2  = (const float*)d_in[6];
    const float* w3  = (const float*)d_in[7];
    const float* b3  = (const float*)d_in[8];
    float* out = (float*)d_out;

    float* warped = nullptr;
    float* corr   = nullptr;
    float* facc   = nullptr;
    cudaGetSymbolAddress((void**)&warped, g_warped);
    cudaGetSymbolAddress((void**)&corr, g_corr);
    cudaGetSymbolAddress((void**)&facc, g_facc);

    const int sm1 = 59 * 27 * 8 * (int)sizeof(float);   // 50976
    const int sm2 = 16 * 27 * 8 * (int)sizeof(float);   // 13824
    const int sm3 = 16 * 27 * 3 * (int)sizeof(float);   //  5184

    cudaFuncSetAttribute((const void*)&convsp_kernel<16, 27, 16, 16, 8, 24, false>,
                         cudaFuncAttributeMaxDynamicSharedMemorySize, sm1);
    cudaFuncSetAttribute((const void*)&convsp_kernel<16, 0, 0, 16, 8, 24, true>,
                         cudaFuncAttributeMaxDynamicSharedMemorySize, sm2);
    cudaFuncSetAttribute((const void*)&convsp_kernel<16, 0, 0, 3, 3, 24, false>,
                         cudaFuncAttributeMaxDynamicSharedMemorySize, sm3);

    int nvox = B_ * VOL;
    warp_kernel<<<(nvox + 255) / 256, 256>>>(src, dvf);

    dim3 cblk(16, 16);
    dim3 cgrd(3, 6, 8 * B_);
    corrp_kernel<<<cgrd, cblk>>>(tgt);

    dim3 blk(32, 4);
    dim3 g16(3, 24, 4 * 2 * B_);   // ZC=24 (NZC=4), NCG=2 -> 1152 blocks
    dim3 g3(3, 24, 4 * 1 * B_);    // ZC=24, NCG=1 -> 576 blocks

    // conv1 fused over its 3 input segments (src, corr, tgt): 59ch -> 16ch, lrelu
    convsp_kernel<16, 27, 16, 16, 8, 24, false>
        <<<g16, blk, sm1>>>(src, corr, tgt, w1, b1, facc, nullptr);
    // conv2 + residual: fsum = f + lrelu(conv(f))
    convsp_kernel<16, 0, 0, 16, 8, 24, true>
        <<<g16, blk, sm2>>>(facc, nullptr, nullptr, w2, b2, warped, facc);
    // conv3: 16 -> 3
    convsp_kernel<16, 0, 0, 3, 3, 24, false>
        <<<g3, blk, sm3>>>(warped, nullptr, nullptr, w3, b3, out, nullptr);
}